// round 11
// baseline (speedup 1.0000x reference)
#include <cuda_runtime.h>

// MultiScaleTrendLoss: loss = mean_{b,t,c} sum_i w_i * ema(pred-target, a_i)[b,t,c]^2
// Exact chunked EMA: y_k = z_k + beta^{k+1} * C.
// K1 (proven): streams data once; A warp-reduced; per-chunk S,E to global.
// K2 (remapped): warp lanes = 32 consecutive chains (coalesced S/E loads),
// 16 segments x 4 chunks per block; smem handoff; warp-0 carry scan; ticket.

#define BB 64
#define TT 4096
#define CC 64
#define CHUNK 64
#define NCHUNK (TT / CHUNK)             // 64
#define NWARPS (BB * NCHUNK)            // 4096
#define THREADS 256
#define BLOCKS (NWARPS * 32 / THREADS)  // 512
#define SEG (BB * NCHUNK * 32)          // 131072 floats per (alpha,comp) plane
#define NCHAIN (3 * 2 * BB * 32)        // 12288 chains
#define NSEGS 16
#define SEGLEN (NCHUNK / NSEGS)         // 4
#define THREADS2 512
#define GRID2 (NCHAIN / 32)             // 384 blocks (32 chains per block)

#define AL0 0.1f
#define AL1 0.3f
#define AL2 0.5f
#define BE0 0.9f
#define BE1 0.7f
#define BE2 0.5f
#define W0f 0.5f
#define W1f 0.3f
#define W2f 0.2f

__host__ __device__ constexpr double dpow(double b, int n) {
    double r = 1.0; for (int i = 0; i < n; ++i) r *= b; return r;
}
__host__ __device__ constexpr double gsum(double beta, int L) {   // sum_{k=1..L} beta^{2k}
    double q = beta * beta; return q * (1.0 - dpow(q, L)) / (1.0 - q);
}
__host__ __device__ constexpr double geo0(double x, int n) {      // sum_{k=0..n-1} x^k
    double s = 0.0, p = 1.0; for (int k = 0; k < n; ++k) { s += p; p *= x; } return s;
}

__device__ __forceinline__ float pick3(int a, float x0, float x1, float x2) {
    return (a == 0) ? x0 : ((a == 1) ? x1 : x2);
}
#define BL_F(a)  pick3(a, (float)dpow(0.9, CHUNK), (float)dpow(0.7, CHUNK), (float)dpow(0.5, CHUNK))
#define G_F(a)   pick3(a, (float)gsum(0.9, CHUNK), (float)gsum(0.7, CHUNK), (float)gsum(0.5, CHUNK))
#define R4_F(a)  pick3(a, (float)(gsum(0.9, CHUNK) * geo0(dpow(0.9, 2 * CHUNK), SEGLEN)), \
                          (float)(gsum(0.7, CHUNK) * geo0(dpow(0.7, 2 * CHUNK), SEGLEN)), \
                          (float)(gsum(0.5, CHUNK) * geo0(dpow(0.5, 2 * CHUNK), SEGLEN)))
#define M4_F(a)  pick3(a, (float)dpow(0.9, CHUNK * SEGLEN), \
                          (float)dpow(0.7, CHUNK * SEGLEN), \
                          (float)dpow(0.5, CHUNK * SEGLEN))
#define W_F(a)   pick3(a, W0f, W1f, W2f)

__device__ float g_S[3 * 2 * SEG];
__device__ float g_E[3 * 2 * SEG];
__device__ float g_Apart[NWARPS];
__device__ float g_D0[2 * BB * 32];
__device__ float g_p2[GRID2];
__device__ unsigned int g_count2 = 0;

// ---------------- Kernel 1: stream data once, emit per-chunk S/E + warp A-partial ----------------
__global__ __launch_bounds__(THREADS) void ema_phase1(
    const float* __restrict__ pred, const float* __restrict__ targ)
{
    const int gw   = (blockIdx.x * blockDim.x + threadIdx.x) >> 5;
    const int lane = threadIdx.x & 31;
    const int b     = gw >> 6;
    const int chunk = gw & (NCHUNK - 1);

    const float2* __restrict__ p2 = reinterpret_cast<const float2*>(pred)
                                    + (b * TT + chunk * CHUNK) * (CC / 2) + lane;
    const float2* __restrict__ q2 = reinterpret_cast<const float2*>(targ)
                                    + (b * TT + chunk * CHUNK) * (CC / 2) + lane;

    constexpr int P = 4;
    float2 bp[P], bq[P];
    #pragma unroll
    for (int i = 0; i < P; ++i) { bp[i] = p2[i * (CC / 2)]; bq[i] = q2[i * (CC / 2)]; }

    float z0x = 0.f, z0y = 0.f, z1x = 0.f, z1y = 0.f, z2x = 0.f, z2y = 0.f;
    float A0x = 0.f, A0y = 0.f, A1x = 0.f, A1y = 0.f, A2x = 0.f, A2y = 0.f;
    float S0x = 0.f, S0y = 0.f, S1x = 0.f, S1y = 0.f, S2x = 0.f, S2y = 0.f;
    float pw0 = BE0, pw1 = BE1, pw2 = BE2;

    const float d0x = bp[0].x - bq[0].x;
    const float d0y = bp[0].y - bq[0].y;

    auto step = [&](float dx, float dy) {
        z0x = fmaf(AL0, dx - z0x, z0x);  z0y = fmaf(AL0, dy - z0y, z0y);
        z1x = fmaf(AL1, dx - z1x, z1x);  z1y = fmaf(AL1, dy - z1y, z1y);
        z2x = fmaf(AL2, dx - z2x, z2x);  z2y = fmaf(AL2, dy - z2y, z2y);
        A0x = fmaf(z0x, z0x, A0x);  A0y = fmaf(z0y, z0y, A0y);
        A1x = fmaf(z1x, z1x, A1x);  A1y = fmaf(z1y, z1y, A1y);
        A2x = fmaf(z2x, z2x, A2x);  A2y = fmaf(z2y, z2y, A2y);
        S0x = fmaf(pw0, z0x, S0x);  S0y = fmaf(pw0, z0y, S0y);
        S1x = fmaf(pw1, z1x, S1x);  S1y = fmaf(pw1, z1y, S1y);
        S2x = fmaf(pw2, z2x, S2x);  S2y = fmaf(pw2, z2y, S2y);
        pw0 *= BE0; pw1 *= BE1; pw2 *= BE2;
    };

    #pragma unroll 8
    for (int k = 0; k < CHUNK - P; ++k) {
        const int slot = k & (P - 1);
        const float dx = bp[slot].x - bq[slot].x;
        const float dy = bp[slot].y - bq[slot].y;
        bp[slot] = p2[(k + P) * (CC / 2)];
        bq[slot] = q2[(k + P) * (CC / 2)];
        step(dx, dy);
    }
    #pragma unroll
    for (int k = CHUNK - P; k < CHUNK; ++k) {
        const int slot = k & (P - 1);
        step(bp[slot].x - bq[slot].x, bp[slot].y - bq[slot].y);
    }

    const int base = (b * NCHUNK + chunk) * 32 + lane;
    g_S[0 * SEG + base] = S0x;  g_S[1 * SEG + base] = S0y;
    g_S[2 * SEG + base] = S1x;  g_S[3 * SEG + base] = S1y;
    g_S[4 * SEG + base] = S2x;  g_S[5 * SEG + base] = S2y;
    g_E[0 * SEG + base] = z0x;  g_E[1 * SEG + base] = z0y;
    g_E[2 * SEG + base] = z1x;  g_E[3 * SEG + base] = z1y;
    g_E[4 * SEG + base] = z2x;  g_E[5 * SEG + base] = z2y;
    if (chunk == 0) {
        g_D0[0 * BB * 32 + b * 32 + lane] = d0x;
        g_D0[1 * BB * 32 + b * 32 + lane] = d0y;
    }

    float ap = W0f * (A0x + A0y) + W1f * (A1x + A1y) + W2f * (A2x + A2y);
    #pragma unroll
    for (int off = 16; off; off >>= 1)
        ap += __shfl_xor_sync(0xffffffffu, ap, off);
    if (lane == 0) g_Apart[gw] = ap;
}

// ------- Kernel 2: lanes = consecutive chains (coalesced); 16 segs/block -------
__global__ __launch_bounds__(THREADS2) void ema_phase2(float* __restrict__ out)
{
    const int tid  = threadIdx.x;
    const int s    = tid >> 5;            // segment 0..15 (one warp per segment)
    const int lane = tid & 31;            // chain-local (== lane_c)
    const int ac   = blockIdx.x >> 6;     // alpha*2+comp, 0..5
    const int b    = blockIdx.x & (BB - 1);
    const int a    = ac >> 1;

    const float bl = BL_F(a);
    const float G  = G_F(a);

    // layout: g_{S,E}[ac*SEG + (b*NCHUNK + chunkIndex)*32 + lane_c]
    const int i0 = ac * SEG + (b * NCHUNK + s * SEGLEN) * 32 + lane;

    float Sr[SEGLEN], Er[SEGLEN];
    #pragma unroll
    for (int k = 0; k < SEGLEN; ++k) Sr[k] = g_S[i0 + k * 32];   // coalesced across lanes
    #pragma unroll
    for (int k = 0; k < SEGLEN; ++k) Er[k] = g_E[i0 + k * 32];

    float m = 1.f, L = 0.f, Pv = 0.f, Qv = 0.f;
    #pragma unroll
    for (int k = 0; k < SEGLEN; ++k) {
        Pv += 2.f * L * Sr[k] + L * L * G;
        Qv += 2.f * m * fmaf(G, L, Sr[k]);
        m *= bl;
        L  = fmaf(bl, L, Er[k]);
    }

    __shared__ float sP[NSEGS * 32], sQ[NSEGS * 32], sL[NSEGS * 32];
    sP[s * 32 + lane] = Pv;  sQ[s * 32 + lane] = Qv;  sL[s * 32 + lane] = L;
    __syncthreads();

    if (tid < 32) {                       // warp 0: scan all 16 segments per chain
        const int comp = ac & 1;
        const float Rc = R4_F(a);
        const float M4 = M4_F(a);
        const float Wt = W_F(a);

        float C = g_D0[comp * (BB * 32) + b * 32 + tid];
        float loss = 0.f;
        #pragma unroll
        for (int ss = 0; ss < NSEGS; ++ss) {
            const int j = ss * 32 + tid;
            loss += sP[j] + sQ[j] * C + Rc * C * C;
            C = fmaf(M4, C, sL[j]);
        }
        float v = Wt * loss;
        #pragma unroll
        for (int off = 16; off; off >>= 1)
            v += __shfl_xor_sync(0xffffffffu, v, off);
        if (tid == 0) g_p2[blockIdx.x] = v;
    }

    // deterministic last-block final reduce (cross terms + A partials)
    __threadfence();
    __syncthreads();
    __shared__ unsigned int s_isLast;
    if (tid == 0) {
        unsigned int tk = atomicAdd(&g_count2, 1u);
        s_isLast = (tk == (unsigned int)(GRID2 - 1));
    }
    __syncthreads();
    if (s_isLast) {
        float w = 0.f;
        for (int i = tid; i < GRID2; i += THREADS2) w += g_p2[i];
        for (int i = tid; i < NWARPS; i += THREADS2) w += g_Apart[i];
        #pragma unroll
        for (int off = 16; off; off >>= 1)
            w += __shfl_xor_sync(0xffffffffu, w, off);
        __shared__ float sm2[16];
        if ((tid & 31) == 0) sm2[tid >> 5] = w;
        __syncthreads();
        if (tid == 0) {
            float tot = 0.f;
            #pragma unroll
            for (int i = 0; i < 16; ++i) tot += sm2[i];
            out[0] = tot * (1.0f / ((float)BB * (float)TT * (float)CC));
            g_count2 = 0;
        }
    }
}

extern "C" void kernel_launch(void* const* d_in, const int* in_sizes, int n_in,
                              void* d_out, int out_size)
{
    const float* pred = (const float*)d_in[0];
    const float* targ = (const float*)d_in[1];
    float* out = (float*)d_out;
    (void)in_sizes; (void)n_in; (void)out_size;

    ema_phase1<<<BLOCKS, THREADS>>>(pred, targ);
    ema_phase2<<<GRID2, THREADS2>>>(out);
}

// round 12
// speedup vs baseline: 1.0645x; 1.0645x over previous
#include <cuda_runtime.h>

// MultiScaleTrendLoss: loss = mean_{b,t,c} sum_i w_i * ema(pred-target, a_i)[b,t,c]^2
// Exact chunked EMA: y_k = z_k + beta^{k+1} * C.
// K1: 8 warps/block = 8 consecutive 64-row chunks of one b. Per-chunk (S,E) ->
// smem -> folded to one 512-row block-segment (P,Q,L) per (alpha,comp,lane).
// Only 1.2 MB hits global (survives k1's L2 thrash cheaply). A (sum z^2) has no
// carry interaction -> block scalar. K2: 8-segment carry scan + ticket reduce.

#define BB 64
#define TT 4096
#define CC 64
#define CHUNK 64
#define NCHUNK (TT / CHUNK)             // 64
#define WPB 8                           // warps (=chunks) per k1 block
#define NBSEG (NCHUNK / WPB)            // 8 block-segments per b
#define GRID1 (BB * NBSEG)              // 512
#define THREADS 256
#define NCHAIN (3 * 2 * BB * 32)        // 12288 chains (ac, b, lane)
#define GRID2 (NCHAIN / 32)             // 384
#define THREADS2 256

#define AL0 0.1f
#define AL1 0.3f
#define AL2 0.5f
#define BE0 0.9f
#define BE1 0.7f
#define BE2 0.5f
#define W0f 0.5f
#define W1f 0.3f
#define W2f 0.2f

__host__ __device__ constexpr double dpow(double b, int n) {
    double r = 1.0; for (int i = 0; i < n; ++i) r *= b; return r;
}
__host__ __device__ constexpr double gsum(double beta, int L) {   // sum_{k=1..L} beta^{2k}
    double q = beta * beta; return q * (1.0 - dpow(q, L)) / (1.0 - q);
}
__host__ __device__ constexpr double geo0(double x, int n) {      // sum_{k=0..n-1} x^k
    double s = 0.0, p = 1.0; for (int k = 0; k < n; ++k) { s += p; p *= x; } return s;
}

__device__ __forceinline__ float pick3(int a, float x0, float x1, float x2) {
    return (a == 0) ? x0 : ((a == 1) ? x1 : x2);
}
// chunk-level (64 rows)
#define BL_F(a)   pick3(a, (float)dpow(0.9, CHUNK), (float)dpow(0.7, CHUNK), (float)dpow(0.5, CHUNK))
#define G_F(a)    pick3(a, (float)gsum(0.9, CHUNK), (float)gsum(0.7, CHUNK), (float)gsum(0.5, CHUNK))
// segment-level (512 rows = 8 chunks)
#define M512_F(a) pick3(a, (float)dpow(0.9, CHUNK * WPB), \
                           (float)dpow(0.7, CHUNK * WPB), \
                           (float)dpow(0.5, CHUNK * WPB))
#define R512_F(a) pick3(a, (float)(gsum(0.9, CHUNK) * geo0(dpow(0.9, 2 * CHUNK), WPB)), \
                           (float)(gsum(0.7, CHUNK) * geo0(dpow(0.7, 2 * CHUNK), WPB)), \
                           (float)(gsum(0.5, CHUNK) * geo0(dpow(0.5, 2 * CHUNK), WPB)))
#define W_F(a)    pick3(a, W0f, W1f, W2f)

__device__ float g_P[NBSEG * NCHAIN];   // 98304 floats
__device__ float g_Q[NBSEG * NCHAIN];
__device__ float g_L[NBSEG * NCHAIN];
__device__ float g_Ap[GRID1];
__device__ float g_D0[2 * BB * 32];
__device__ float g_p2[GRID2];
__device__ unsigned int g_count2 = 0;

// ============ Kernel 1: stream + block-local segment fold ============
__global__ __launch_bounds__(THREADS) void ema_k1(
    const float* __restrict__ pred, const float* __restrict__ targ)
{
    const int tid  = threadIdx.x;
    const int w    = tid >> 5;
    const int lane = tid & 31;
    const int b    = blockIdx.x >> 3;            // / NBSEG
    const int bs   = blockIdx.x & (NBSEG - 1);
    const int chunk = bs * WPB + w;              // 0..63

    __shared__ float sS[6 * THREADS];            // [ac][w*32+lane]
    __shared__ float sE[6 * THREADS];
    __shared__ float sA[WPB];

    // ---- streaming phase (proven loop) ----
    {
        const float2* __restrict__ p2 = reinterpret_cast<const float2*>(pred)
                                        + (b * TT + chunk * CHUNK) * (CC / 2) + lane;
        const float2* __restrict__ q2 = reinterpret_cast<const float2*>(targ)
                                        + (b * TT + chunk * CHUNK) * (CC / 2) + lane;

        constexpr int P = 4;
        float2 bp[P], bq[P];
        #pragma unroll
        for (int i = 0; i < P; ++i) { bp[i] = p2[i * (CC / 2)]; bq[i] = q2[i * (CC / 2)]; }

        float z0x = 0.f, z0y = 0.f, z1x = 0.f, z1y = 0.f, z2x = 0.f, z2y = 0.f;
        float A0x = 0.f, A0y = 0.f, A1x = 0.f, A1y = 0.f, A2x = 0.f, A2y = 0.f;
        float S0x = 0.f, S0y = 0.f, S1x = 0.f, S1y = 0.f, S2x = 0.f, S2y = 0.f;
        float pw0 = BE0, pw1 = BE1, pw2 = BE2;

        const float d0x = bp[0].x - bq[0].x;
        const float d0y = bp[0].y - bq[0].y;

        auto step = [&](float dx, float dy) {
            z0x = fmaf(AL0, dx - z0x, z0x);  z0y = fmaf(AL0, dy - z0y, z0y);
            z1x = fmaf(AL1, dx - z1x, z1x);  z1y = fmaf(AL1, dy - z1y, z1y);
            z2x = fmaf(AL2, dx - z2x, z2x);  z2y = fmaf(AL2, dy - z2y, z2y);
            A0x = fmaf(z0x, z0x, A0x);  A0y = fmaf(z0y, z0y, A0y);
            A1x = fmaf(z1x, z1x, A1x);  A1y = fmaf(z1y, z1y, A1y);
            A2x = fmaf(z2x, z2x, A2x);  A2y = fmaf(z2y, z2y, A2y);
            S0x = fmaf(pw0, z0x, S0x);  S0y = fmaf(pw0, z0y, S0y);
            S1x = fmaf(pw1, z1x, S1x);  S1y = fmaf(pw1, z1y, S1y);
            S2x = fmaf(pw2, z2x, S2x);  S2y = fmaf(pw2, z2y, S2y);
            pw0 *= BE0; pw1 *= BE1; pw2 *= BE2;
        };

        #pragma unroll 8
        for (int k = 0; k < CHUNK - P; ++k) {
            const int slot = k & (P - 1);
            const float dx = bp[slot].x - bq[slot].x;
            const float dy = bp[slot].y - bq[slot].y;
            bp[slot] = p2[(k + P) * (CC / 2)];
            bq[slot] = q2[(k + P) * (CC / 2)];
            step(dx, dy);
        }
        #pragma unroll
        for (int k = CHUNK - P; k < CHUNK; ++k) {
            const int slot = k & (P - 1);
            step(bp[slot].x - bq[slot].x, bp[slot].y - bq[slot].y);
        }

        const int wl = w * 32 + lane;
        sS[0 * THREADS + wl] = S0x;  sS[1 * THREADS + wl] = S0y;
        sS[2 * THREADS + wl] = S1x;  sS[3 * THREADS + wl] = S1y;
        sS[4 * THREADS + wl] = S2x;  sS[5 * THREADS + wl] = S2y;
        sE[0 * THREADS + wl] = z0x;  sE[1 * THREADS + wl] = z0y;
        sE[2 * THREADS + wl] = z1x;  sE[3 * THREADS + wl] = z1y;
        sE[4 * THREADS + wl] = z2x;  sE[5 * THREADS + wl] = z2y;

        if (chunk == 0) {                // virtual carry: C0 = d at t=0
            g_D0[0 * (BB * 32) + b * 32 + lane] = d0x;
            g_D0[1 * (BB * 32) + b * 32 + lane] = d0y;
        }

        float ap = W0f * (A0x + A0y) + W1f * (A1x + A1y) + W2f * (A2x + A2y);
        #pragma unroll
        for (int off = 16; off; off >>= 1)
            ap += __shfl_xor_sync(0xffffffffu, ap, off);
        if (lane == 0) sA[w] = ap;
    }
    __syncthreads();

    // ---- fold 8 chunks -> one 512-row segment (P,Q,L) per (ac, lane) ----
    if (tid < 6 * 32) {
        const int ac    = tid >> 5;
        const int lane2 = tid & 31;
        const int a     = ac >> 1;
        const float bl = BL_F(a);
        const float G  = G_F(a);

        float m = 1.f, L = 0.f, Pv = 0.f, Qv = 0.f;
        #pragma unroll
        for (int j = 0; j < WPB; ++j) {
            const float Sv = sS[ac * THREADS + j * 32 + lane2];
            const float Ev = sE[ac * THREADS + j * 32 + lane2];
            Pv += 2.f * L * Sv + L * L * G;
            Qv += 2.f * m * fmaf(G, L, Sv);
            m *= bl;
            L  = fmaf(bl, L, Ev);
        }
        const int chain = ac * (BB * 32) + b * 32 + lane2;
        g_P[bs * NCHAIN + chain] = Pv;
        g_Q[bs * NCHAIN + chain] = Qv;
        g_L[bs * NCHAIN + chain] = L;
    }
    if (tid == 0) {
        float apb = 0.f;
        #pragma unroll
        for (int i = 0; i < WPB; ++i) apb += sA[i];
        g_Ap[blockIdx.x] = apb;
    }
}

// ============ Kernel 2: 8-segment carry scan per chain + final reduce ============
__global__ __launch_bounds__(THREADS2) void ema_k2(float* __restrict__ out)
{
    const int tid  = threadIdx.x;
    const int s    = tid >> 5;                 // segment 0..7 (one warp each)
    const int lane = tid & 31;                 // chain-local
    const int ac   = blockIdx.x >> 6;          // 0..5
    const int b    = blockIdx.x & (BB - 1);
    const int a    = ac >> 1;

    const int idx = s * NCHAIN + blockIdx.x * 32 + lane;   // coalesced per warp
    const float Pv = g_P[idx];
    const float Qv = g_Q[idx];
    const float Lv = g_L[idx];

    __shared__ float sP[NBSEG * 32], sQ[NBSEG * 32], sL[NBSEG * 32];
    sP[s * 32 + lane] = Pv;  sQ[s * 32 + lane] = Qv;  sL[s * 32 + lane] = Lv;
    __syncthreads();

    if (tid < 32) {                            // warp 0 scans 8 segments per chain
        const int comp = ac & 1;
        const float Rc = R512_F(a);
        const float M  = M512_F(a);
        const float Wt = W_F(a);

        float C = g_D0[comp * (BB * 32) + b * 32 + tid];
        float loss = 0.f;
        #pragma unroll
        for (int ss = 0; ss < NBSEG; ++ss) {
            const int j = ss * 32 + tid;
            loss += sP[j] + sQ[j] * C + Rc * C * C;
            C = fmaf(M, C, sL[j]);
        }
        float v = Wt * loss;
        #pragma unroll
        for (int off = 16; off; off >>= 1)
            v += __shfl_xor_sync(0xffffffffu, v, off);
        if (tid == 0) g_p2[blockIdx.x] = v;
    }

    // deterministic last-block final reduce (cross terms + A partials)
    __threadfence();
    __syncthreads();
    __shared__ unsigned int s_isLast;
    if (tid == 0) {
        unsigned int tk = atomicAdd(&g_count2, 1u);
        s_isLast = (tk == (unsigned int)(GRID2 - 1));
    }
    __syncthreads();
    if (s_isLast) {
        float w = 0.f;
        for (int i = tid; i < GRID2; i += THREADS2) w += g_p2[i];
        for (int i = tid; i < GRID1; i += THREADS2) w += g_Ap[i];
        #pragma unroll
        for (int off = 16; off; off >>= 1)
            w += __shfl_xor_sync(0xffffffffu, w, off);
        __shared__ float sm2[8];
        if ((tid & 31) == 0) sm2[tid >> 5] = w;
        __syncthreads();
        if (tid == 0) {
            float tot = 0.f;
            #pragma unroll
            for (int i = 0; i < 8; ++i) tot += sm2[i];
            out[0] = tot * (1.0f / ((float)BB * (float)TT * (float)CC));
            g_count2 = 0;
        }
    }
}

extern "C" void kernel_launch(void* const* d_in, const int* in_sizes, int n_in,
                              void* d_out, int out_size)
{
    const float* pred = (const float*)d_in[0];
    const float* targ = (const float*)d_in[1];
    float* out = (float*)d_out;
    (void)in_sizes; (void)n_in; (void)out_size;

    ema_k1<<<GRID1, THREADS>>>(pred, targ);
    ema_k2<<<GRID2, THREADS2>>>(out);
}